// round 10
// baseline (speedup 1.0000x reference)
#include <cuda_runtime.h>
#include <cuda_bf16.h>
#include <cuda_fp16.h>
#include <cuda_fp8.h>
#include <cstdint>

#define N_ROWS      12288        // L1_INPUT_SIZE
#define N_COLS      1030         // L1_OUTPUT_SIZE
#define HID         1024
#define STRIDE8     1040         // padded fp8 row stride bytes (16B multiple)
#define BATCH       8192
#define NFEAT       32
#define L2IN        2048
#define W_SCALE     128.0f       // weight scale into e4m3 normal range
#define INV_SCALE   0.0078125f   // 1/128
#define PSQT_K      0.08f        // 0.5 / (400/64)
#define GPR         260          // groups of 4 cols per row (260*4 = 1040)
#define ROWS_PER_CTA 2

// fp8(e4m3) copy of W1*128 (module-static, no runtime alloc)
__device__ __align__(128) unsigned char g_W1f8[(size_t)N_ROWS * STRIDE8];

// ---------------------------------------------------------------------------
// W1 fp32 -> fp8 conversion (R2-proven shape: u32 store per thread)
// ---------------------------------------------------------------------------
__global__ void convert_kernel(const float* __restrict__ W1) {
    int gid = blockIdx.x * blockDim.x + threadIdx.x;
    if (gid >= N_ROWS * GPR) return;
    const int r   = gid / GPR;
    const int g   = gid - r * GPR;
    const int col = g * 4;
    const float* src = W1 + (size_t)r * N_COLS + col;

    float4 w;
    if (col + 4 <= N_COLS) {
        const float2 a = *reinterpret_cast<const float2*>(src);
        const float2 b = *reinterpret_cast<const float2*>(src + 2);
        w = make_float4(a.x, a.y, b.x, b.y);
    } else {
        w.x = (col + 0 < N_COLS) ? src[0] : 0.f;
        w.y = (col + 1 < N_COLS) ? src[1] : 0.f;
        w.z = (col + 2 < N_COLS) ? src[2] : 0.f;
        w.w = (col + 3 < N_COLS) ? src[3] : 0.f;
    }
    const __nv_fp8x2_storage_t lo =
        __nv_cvt_float2_to_fp8x2(make_float2(w.x * W_SCALE, w.y * W_SCALE),
                                 __NV_SATFINITE, __NV_E4M3);
    const __nv_fp8x2_storage_t hi =
        __nv_cvt_float2_to_fp8x2(make_float2(w.z * W_SCALE, w.w * W_SCALE),
                                 __NV_SATFINITE, __NV_E4M3);
    const uint32_t packed = (uint32_t)lo | ((uint32_t)hi << 16);
    *reinterpret_cast<uint32_t*>(g_W1f8 + (size_t)r * STRIDE8 + col) = packed;
}

// ---------------------------------------------------------------------------
// unpack u32 (4×e4m3) -> two half2, fused multiply-accumulate with vh
// ---------------------------------------------------------------------------
__device__ __forceinline__ void fma4_fp8(half2& a0, half2& a1, uint32_t w, half2 vh) {
    uint32_t h0, h1;
    asm("{\n\t"
        ".reg .b16 lo, hi;\n\t"
        "mov.b32 {lo, hi}, %2;\n\t"
        "cvt.rn.f16x2.e4m3x2 %0, lo;\n\t"
        "cvt.rn.f16x2.e4m3x2 %1, hi;\n\t"
        "}" : "=r"(h0), "=r"(h1) : "r"(w));
    a0 = __hfma2(*reinterpret_cast<half2*>(&h0), vh, a0);
    a1 = __hfma2(*reinterpret_cast<half2*>(&h1), vh, a1);
}

// ---------------------------------------------------------------------------
// Main fused kernel: 128 threads = 2 batch rows in parallel.
// Warp w: row = w>>1, column-half = w&1. Lane owns 16 fp8 cols per side
// (LDG.128), with a 2-deep uint4 prefetch pipeline (2KB in flight / warp).
// ---------------------------------------------------------------------------
__global__ __launch_bounds__(128)
void fwd_kernel(const int*   __restrict__ x,
                const int*   __restrict__ y,
                const float* __restrict__ v,
                const int*   __restrict__ s,
                const float* __restrict__ b1,
                const float* __restrict__ W2,
                const float* __restrict__ b2,
                float*       __restrict__ out)
{
    __shared__ int2     sxy[ROWS_PER_CTA][NFEAT + 2];  // {offx, offy}; +2 pad for prefetch tail
    __shared__ uint32_t svh[ROWS_PER_CTA][NFEAT];      // v as half2 bits
    __shared__ int      sss[ROWS_PER_CTA];
    __shared__ float    red[4];

    const int b0 = blockIdx.x * ROWS_PER_CTA;
    const int t  = threadIdx.x;

    // ---- prologue: threads 0..63 build both rows' records ----
    if (t < 64) {
        const int row = t >> 5;
        const int a   = t & 31;
        const int gi  = (b0 + row) * NFEAT + a;
        sxy[row][a] = make_int2(x[gi] * STRIDE8, y[gi] * STRIDE8);
        const half2 vh = __float2half2_rn(v[gi]);
        svh[row][a] = *reinterpret_cast<const uint32_t*>(&vh);
    } else if (t < 68) {                   // pad entries for branch-free tail prefetch
        sxy[(t - 64) >> 1][NFEAT + ((t - 64) & 1)] = make_int2(0, 0);
    } else if (t < 68 + ROWS_PER_CTA) {
        sss[t - 68] = s[b0 + (t - 68)];
    }
    __syncthreads();

    const int w   = t >> 5;               // warp id 0..3
    const int L   = t & 31;               // lane
    const int row = w >> 1;               // batch row within CTA
    const int h   = w & 1;                // column half
    const int col0 = h * 512 + L * 16;    // 16 fp8 columns per thread per side
    const unsigned char* basep = g_W1f8 + col0;
    const int2*     offs = sxy[row];
    const uint32_t* vhp  = svh[row];

    // ---- prime the 2-deep prefetch pipeline ----
    uint4 px[2], py[2];
#pragma unroll
    for (int i = 0; i < 2; ++i) {
        const int2 o = offs[i];
        px[i] = *reinterpret_cast<const uint4*>(basep + o.x);
        py[i] = *reinterpret_cast<const uint4*>(basep + o.y);
    }

    half2 ax[8], ay[8];
#pragma unroll
    for (int j = 0; j < 8; ++j) { ax[j] = __float2half2_rn(0.f); ay[j] = __float2half2_rn(0.f); }

#pragma unroll 4
    for (int a = 0; a < NFEAT; ++a) {
        const int slot = a & 1;
        const uint4 wx = px[slot];
        const uint4 wy = py[slot];
        const int2  on = offs[a + 2];      // one LDS.64 for both next offsets
        px[slot] = *reinterpret_cast<const uint4*>(basep + on.x);
        py[slot] = *reinterpret_cast<const uint4*>(basep + on.y);

        half2 vh; *reinterpret_cast<uint32_t*>(&vh) = vhp[a];
        fma4_fp8(ax[0], ax[1], wx.x, vh);
        fma4_fp8(ax[2], ax[3], wx.y, vh);
        fma4_fp8(ax[4], ax[5], wx.z, vh);
        fma4_fp8(ax[6], ax[7], wx.w, vh);
        fma4_fp8(ay[0], ay[1], wy.x, vh);
        fma4_fp8(ay[2], ay[3], wy.y, vh);
        fma4_fp8(ay[4], ay[5], wy.z, vh);
        fma4_fp8(ay[6], ay[7], wy.w, vh);
    }

    // ---- epilogue: relu(acc/128 + b1) dot W2[ss] over 16 cols/side ----
    const int ss = sss[row];
    const float* b1seg = b1 + col0;
    const float* w2x   = W2 + (size_t)ss * L2IN + col0;
    const float* w2y   = w2x + HID;

    float local = 0.f;
#pragma unroll
    for (int j = 0; j < 4; ++j) {
        const float4 bb  = reinterpret_cast<const float4*>(b1seg)[j];
        const float4 wwx = reinterpret_cast<const float4*>(w2x)[j];
        const float4 wwy = reinterpret_cast<const float4*>(w2y)[j];
        const float2 fx0 = __half22float2(ax[2 * j]);
        const float2 fx1 = __half22float2(ax[2 * j + 1]);
        const float2 fy0 = __half22float2(ay[2 * j]);
        const float2 fy1 = __half22float2(ay[2 * j + 1]);
        local = fmaf(fmaxf(fmaf(fx0.x, INV_SCALE, bb.x), 0.f), wwx.x, local);
        local = fmaf(fmaxf(fmaf(fx0.y, INV_SCALE, bb.y), 0.f), wwx.y, local);
        local = fmaf(fmaxf(fmaf(fx1.x, INV_SCALE, bb.z), 0.f), wwx.z, local);
        local = fmaf(fmaxf(fmaf(fx1.y, INV_SCALE, bb.w), 0.f), wwx.w, local);
        local = fmaf(fmaxf(fmaf(fy0.x, INV_SCALE, bb.x), 0.f), wwy.x, local);
        local = fmaf(fmaxf(fmaf(fy0.y, INV_SCALE, bb.y), 0.f), wwy.y, local);
        local = fmaf(fmaxf(fmaf(fy1.x, INV_SCALE, bb.z), 0.f), wwy.z, local);
        local = fmaf(fmaxf(fmaf(fy1.y, INV_SCALE, bb.w), 0.f), wwy.w, local);
    }

    // ---- psqt term: (x2 - y2) * PSQT_K ; b1 cancels in the difference ----
    // warp-half h==0 -> x side (+), h==1 -> y side (-); lane L = feature L
    {
        const int2 o = offs[L];
        const int off = h ? o.y : o.x;
        const unsigned char wb = g_W1f8[(size_t)off + HID + ss];
        const float wgt = __half2float(
            __nv_cvt_fp8_to_halfraw((__nv_fp8_storage_t)wb, __NV_E4M3));
        half2 vh; *reinterpret_cast<uint32_t*>(&vh) = vhp[L];
        const float p = __half2float(__low2half(vh)) * wgt * (PSQT_K * INV_SCALE);
        local += h ? -p : p;
    }

    // ---- warp reduction, then 2-warp combine per row ----
#pragma unroll
    for (int o = 16; o > 0; o >>= 1)
        local += __shfl_down_sync(0xffffffffu, local, o);
    if (L == 0) red[w] = local;
    __syncthreads();
    if (t == 0)
        out[b0]     = 1.0f / (1.0f + expf(-(red[0] + red[1] + b2[sss[0]])));
    else if (t == 64)
        out[b0 + 1] = 1.0f / (1.0f + expf(-(red[2] + red[3] + b2[sss[1]])));
}

// ---------------------------------------------------------------------------
extern "C" void kernel_launch(void* const* d_in, const int* in_sizes, int n_in,
                              void* d_out, int out_size)
{
    const int*   x  = (const int*)  d_in[0];
    const int*   y  = (const int*)  d_in[1];
    const float* v  = (const float*)d_in[2];
    const int*   s  = (const int*)  d_in[3];
    const float* W1 = (const float*)d_in[4];
    const float* b1 = (const float*)d_in[5];
    const float* W2 = (const float*)d_in[6];
    const float* b2 = (const float*)d_in[7];
    float* out = (float*)d_out;

    const int total = N_ROWS * GPR;
    convert_kernel<<<(total + 255) / 256, 256>>>(W1);
    fwd_kernel<<<BATCH / ROWS_PER_CTA, 128>>>(x, y, v, s, b1, W2, b2, out);
}